// round 10
// baseline (speedup 1.0000x reference)
#include <cuda_runtime.h>
#include <cstdint>

// ---------------- problem constants ----------------
#define B_    32
#define C_    256
#define O_    256
#define H_    49
#define P_    (H_ * H_)        // 2401
#define PAD   51
#define M_    (B_ * P_)        // 76832
#define KTOT  (7 * C_)         // 1792
#define KC    32               // K per pipeline chunk
#define NCHUNK (KTOT / KC)     // 56
#define STAGES 2               // 2 stages @ stride 40 -> 81.9 KB -> 2 CTAs/SM
#define MT    128              // M rows per CTA
#define GRID_M ((M_ + MT - 1) / MT)   // 601

#define ASTRIDE 40                      // smem row stride in floats (conflict-free LDS.64)
#define STAGE_F (MT * ASTRIDE)          // 5120 floats per A (or B) stage
#define DYN_SMEM (2 * STAGES * STAGE_F * 4)   // 81920 bytes

// DIRS offsets in padded channels-last space: (dy*PAD+dx)*C_
__constant__ int c_tapoff[7] = { 0, 13056, 256, -12800, -13056, -256, 12800 };

// ---------------- scratch ----------------
__device__ float g_xpad[B_ * PAD * PAD * C_];   // [B,51,51,C] channels-last, c-permuted, tf32
__device__ float g_wb[O_ * KTOT];               // [o][k], k = tap*256 + perm(c), tf32

// channel-pair permutation: within each 8-group, position order [0,4,1,5,2,6,3,7]
// so fragment pairs (k, k+4) are adjacent in memory -> LDS.64
__device__ __forceinline__ int permc(int c) {
    int c8 = c & 7;
    int p8 = (c8 < 4) ? (c8 << 1) : (((c8 - 4) << 1) | 1);
    return (c & ~7) | p8;
}

// ---------------- helpers ----------------
__device__ __forceinline__ float to_tf32(float f) {
    uint32_t u;
    asm("cvt.rna.tf32.f32 %0, %1;" : "=r"(u) : "f"(f));
    return __uint_as_float(u);
}
__device__ __forceinline__ void mma8(float* c, const uint32_t* a, const uint32_t* b) {
    asm volatile(
        "mma.sync.aligned.m16n8k8.row.col.f32.tf32.tf32.f32 "
        "{%0,%1,%2,%3}, {%4,%5,%6,%7}, {%8,%9}, {%0,%1,%2,%3};"
        : "+f"(c[0]), "+f"(c[1]), "+f"(c[2]), "+f"(c[3])
        : "r"(a[0]), "r"(a[1]), "r"(a[2]), "r"(a[3]), "r"(b[0]), "r"(b[1]));
}
#define CP_ASYNC16(dst, src) \
    asm volatile("cp.async.cg.shared.global [%0], [%1], 16;" :: "r"(dst), "l"(src))
#define CP_COMMIT() asm volatile("cp.async.commit_group;")
#define CP_WAIT(n)  asm volatile("cp.async.wait_group %0;" :: "n"(n))

// ---------------- prep kernels ----------------
__global__ void zero_halo_kernel() {      // zero only the 200 boundary cells of xpad
    int t = blockIdx.x * blockDim.x + threadIdx.x;
    const int total = B_ * 200 * 64;
    if (t >= total) return;
    int q = t & 63;
    int cell = (t >> 6) % 200;
    int b = t / (200 * 64);
    int h, w;
    if      (cell < 51)  { h = 0;  w = cell; }
    else if (cell < 102) { h = 50; w = cell - 51; }
    else if (cell < 151) { h = cell - 101; w = 0; }
    else                 { h = cell - 150; w = 50; }
    ((float4*)(g_xpad + ((size_t)(b * PAD + h) * PAD + w) * C_))[q] =
        make_float4(0.f, 0.f, 0.f, 0.f);
}

__global__ void prep_wb_kernel(const float* __restrict__ w) {
    int idx = blockIdx.x * blockDim.x + threadIdx.x;
    if (idx < O_ * KTOT) {
        int o = idx / KTOT;
        int k = idx - o * KTOT;
        int tap = k >> 8, c = k & 255;
        g_wb[o * KTOT + tap * 256 + permc(c)] = to_tf32(w[(o * C_ + c) * 7 + tap]);
    }
}

__global__ void prep_x_kernel(const float* __restrict__ x) {
    __shared__ float tile[32][33];
    const int b = blockIdx.z, c0 = blockIdx.y * 32, hw0 = blockIdx.x * 32;
    const int tx = threadIdx.x, ty = threadIdx.y;
#pragma unroll
    for (int i = 0; i < 4; i++) {
        int c = c0 + ty + i * 8, hw = hw0 + tx;
        tile[ty + i * 8][tx] = (hw < P_) ? x[((size_t)b * C_ + c) * P_ + hw] : 0.f;
    }
    __syncthreads();
#pragma unroll
    for (int i = 0; i < 4; i++) {
        int hw = hw0 + ty + i * 8;
        if (hw < P_) {
            int h = hw / H_, w = hw - h * H_;
            bool mk = (unsigned)(h + w - 24) <= 48u;
            float v = mk ? to_tf32(tile[tx][ty + i * 8]) : 0.f;
            g_xpad[((size_t)(b * PAD + h + 1) * PAD + (w + 1)) * C_ + permc(c0 + tx)] = v;
        }
    }
}

// ---------------- main: tf32 mma.sync GEMM, 128x128 tile, LDS.64 fragments ----------------
__global__ __launch_bounds__(256, 2)
void hexconv_mma_kernel(const float* __restrict__ bias, float* __restrict__ out) {
    extern __shared__ __align__(16) float smem[];
    float* sA = smem;                     // [STAGES][128][40]
    float* sB = smem + STAGES * STAGE_F;  // [STAGES][128][40]
    __shared__ int rbase[MT];

    const int tid = threadIdx.x, wid = tid >> 5, lane = tid & 31;
    const int r0 = blockIdx.x * MT;
    const int nb = blockIdx.y;            // N tile: o-offset nb*128

    if (tid < MT) {
        int r = r0 + tid;
        if (r >= M_) r = M_ - 1;
        int b = r / P_, hw = r - b * P_, h = hw / H_, w = hw - h * H_;
        rbase[tid] = ((b * PAD + h + 1) * PAD + (w + 1)) * C_;
    }
    __syncthreads();

    // loader mapping: thread covers 4 rows (lrow+32i), one 16B quad per row
    const int lrow = tid >> 3;            // 0..31
    const int lq   = (tid & 7) * 4;       // 0,4,...,28 floats
    int ra[4];
#pragma unroll
    for (int i = 0; i < 4; i++) ra[i] = rbase[lrow + 32 * i];

    const uint32_t sA_u = (uint32_t)__cvta_generic_to_shared(sA);
    const uint32_t sB_u = (uint32_t)__cvta_generic_to_shared(sB);

    // warp tile: 2 (M) x 4 (N) warps, each 64x32
    const int wm = (wid & 1) * 64;
    const int wn = (wid >> 1) * 32;

    float acc[4][4][4];
#pragma unroll
    for (int mi = 0; mi < 4; mi++)
#pragma unroll
        for (int ni = 0; ni < 4; ni++)
#pragma unroll
            for (int j = 0; j < 4; j++) acc[mi][ni][j] = 0.f;

    auto load_stage = [&](int s, int ch) {
        const int k0 = ch * KC;
        const int offA = c_tapoff[k0 >> 8] + (k0 & 255) + lq;
#pragma unroll
        for (int i = 0; i < 4; i++) {
            uint32_t dA = sA_u + (uint32_t)(s * STAGE_F + (lrow + 32 * i) * ASTRIDE + lq) * 4u;
            CP_ASYNC16(dA, g_xpad + ra[i] + offA);
        }
#pragma unroll
        for (int i = 0; i < 4; i++) {
            uint32_t dB = sB_u + (uint32_t)(s * STAGE_F + (lrow + 32 * i) * ASTRIDE + lq) * 4u;
            CP_ASYNC16(dB, g_wb + (size_t)(nb * 128 + lrow + 32 * i) * KTOT + k0 + lq);
        }
    };

    load_stage(0, 0);
    CP_COMMIT();

    for (int ch = 0; ch < NCHUNK; ch++) {
        CP_WAIT(0);
        __syncthreads();
        if (ch + 1 < NCHUNK) { load_stage((ch + 1) & 1, ch + 1); }
        CP_COMMIT();

        const float* A  = sA + (ch & 1) * STAGE_F;
        const float* Bm = sB + (ch & 1) * STAGE_F;
#pragma unroll
        for (int kk = 0; kk < 4; kk++) {
            const int kp = kk * 8 + 2 * (lane & 3);   // permuted pair position
            uint32_t af[4][4], bf[4][2];
#pragma unroll
            for (int mi = 0; mi < 4; mi++) {
                int m0 = wm + mi * 16 + (lane >> 2);
                float2 alo = *(const float2*)&A[m0 * ASTRIDE + kp];        // (kb, kb+4)
                float2 ahi = *(const float2*)&A[(m0 + 8) * ASTRIDE + kp];
                af[mi][0] = __float_as_uint(alo.x);
                af[mi][1] = __float_as_uint(ahi.x);
                af[mi][2] = __float_as_uint(alo.y);
                af[mi][3] = __float_as_uint(ahi.y);
            }
#pragma unroll
            for (int ni = 0; ni < 4; ni++) {
                int n0 = wn + ni * 8 + (lane >> 2);
                float2 bv = *(const float2*)&Bm[n0 * ASTRIDE + kp];
                bf[ni][0] = __float_as_uint(bv.x);
                bf[ni][1] = __float_as_uint(bv.y);
            }
#pragma unroll
            for (int mi = 0; mi < 4; mi++)
#pragma unroll
                for (int ni = 0; ni < 4; ni++)
                    mma8(acc[mi][ni], af[mi], bf[ni]);
        }
    }

    // ---- epilogue: acc -> smem [o][m] (stride 132), then coalesced store ----
    __syncthreads();
    float* ep = smem;                     // 128*132 floats = 67.6 KB < 80 KB
#pragma unroll
    for (int mi = 0; mi < 4; mi++) {
        int rrow = wm + mi * 16 + (lane >> 2);
#pragma unroll
        for (int ni = 0; ni < 4; ni++) {
            int o = wn + ni * 8 + 2 * (lane & 3);
            ep[o * 132 + rrow]           = acc[mi][ni][0];
            ep[(o + 1) * 132 + rrow]     = acc[mi][ni][1];
            ep[o * 132 + rrow + 8]       = acc[mi][ni][2];
            ep[(o + 1) * 132 + rrow + 8] = acc[mi][ni][3];
        }
    }
    __syncthreads();

    for (int o = wid; o < 128; o += 8) {
        float bv = __ldg(bias + nb * 128 + o);
#pragma unroll
        for (int mb = 0; mb < 128; mb += 32) {
            int m = mb + lane;
            int r = r0 + m;
            if (r < M_) {
                int b = r / P_, hw = r - b * P_, h = hw / H_, w = hw - h * H_;
                bool mk = (unsigned)(h + w - 24) <= 48u;
                float v = mk ? (ep[o * 132 + m] + bv) : 0.f;
                out[((size_t)b * O_ + nb * 128 + o) * P_ + hw] = v;
            }
        }
    }
}

// ---------------- launcher ----------------
extern "C" void kernel_launch(void* const* d_in, const int* in_sizes, int n_in,
                              void* d_out, int out_size) {
    const float* x    = (const float*)d_in[0];   // [32,256,49,49]
    const float* wgt  = (const float*)d_in[1];   // [256,256,7]
    const float* bias = (const float*)d_in[2];   // [256]
    float* out = (float*)d_out;

    { // prep
        int nh = B_ * 200 * 64;
        zero_halo_kernel<<<(nh + 255) / 256, 256>>>();
        int nw = O_ * KTOT;
        prep_wb_kernel<<<(nw + 255) / 256, 256>>>(wgt);
        dim3 g((P_ + 31) / 32, C_ / 32, B_);
        prep_x_kernel<<<g, dim3(32, 8)>>>(x);
    }

    cudaFuncSetAttribute(hexconv_mma_kernel,
                         cudaFuncAttributeMaxDynamicSharedMemorySize, DYN_SMEM);
    dim3 grid(GRID_M, 2);
    hexconv_mma_kernel<<<grid, 256, DYN_SMEM>>>(bias, out);
}

// round 11
// speedup vs baseline: 1.5165x; 1.5165x over previous
#include <cuda_runtime.h>
#include <cstdint>

// ---------------- problem constants ----------------
#define B_    32
#define C_    256
#define O_    256
#define H_    49
#define P_    (H_ * H_)        // 2401
#define PAD   51
#define M_    (B_ * P_)        // 76832
#define KTOT  (7 * C_)         // 1792
#define KC    32               // K per pipeline chunk
#define NCHUNK (KTOT / KC)     // 56
#define STAGES 3
#define MT    128              // M rows per CTA
#define GRID_M ((M_ + MT - 1) / MT)   // 601

#define A_STRIDE 40                     // floats; conflict-free LDS.64 pairs
#define B_STRIDE 136                    // floats; k-major B, conflict-free scalar
#define A_STAGE_F (MT * A_STRIDE)       // 5120
#define B_STAGE_F (KC * B_STRIDE)       // 4352
#define DYN_SMEM (STAGES * (A_STAGE_F + B_STAGE_F) * 4)   // 113664 bytes

// DIRS offsets in padded channels-last space: (dy*PAD+dx)*C_
__constant__ int c_tapoff[7] = { 0, 13056, 256, -12800, -13056, -256, 12800 };

// ---------------- scratch ----------------
__device__ float g_xpad[B_ * PAD * PAD * C_];   // [B,51,51,C] channels-last, c-permuted, tf32
__device__ float g_wbT[KTOT * O_];              // [k][o], k = tap*256 + c (canonical), tf32

// channel-pair permutation: within each 8-group, positions hold [0,4,1,5,2,6,3,7]
// so fragment pairs (k, k+4) are adjacent -> LDS.64. Applied to A only.
__device__ __forceinline__ int permc(int c) {
    int c8 = c & 7;
    int p8 = (c8 < 4) ? (c8 << 1) : (((c8 - 4) << 1) | 1);
    return (c & ~7) | p8;
}

// ---------------- helpers ----------------
__device__ __forceinline__ float to_tf32(float f) {
    uint32_t u;
    asm("cvt.rna.tf32.f32 %0, %1;" : "=r"(u) : "f"(f));
    return __uint_as_float(u);
}
__device__ __forceinline__ void mma8(float* c, const uint32_t* a, const uint32_t* b) {
    asm volatile(
        "mma.sync.aligned.m16n8k8.row.col.f32.tf32.tf32.f32 "
        "{%0,%1,%2,%3}, {%4,%5,%6,%7}, {%8,%9}, {%0,%1,%2,%3};"
        : "+f"(c[0]), "+f"(c[1]), "+f"(c[2]), "+f"(c[3])
        : "r"(a[0]), "r"(a[1]), "r"(a[2]), "r"(a[3]), "r"(b[0]), "r"(b[1]));
}
#define CP_ASYNC16(dst, src) \
    asm volatile("cp.async.cg.shared.global [%0], [%1], 16;" :: "r"(dst), "l"(src))
#define CP_COMMIT() asm volatile("cp.async.commit_group;")
#define CP_WAIT(n)  asm volatile("cp.async.wait_group %0;" :: "n"(n))

// ---------------- prep kernels ----------------
__global__ void zero_halo_kernel() {      // zero only the 200 boundary cells of xpad
    int t = blockIdx.x * blockDim.x + threadIdx.x;
    const int total = B_ * 200 * 64;
    if (t >= total) return;
    int q = t & 63;
    int cell = (t >> 6) % 200;
    int b = t / (200 * 64);
    int h, w;
    if      (cell < 51)  { h = 0;  w = cell; }
    else if (cell < 102) { h = 50; w = cell - 51; }
    else if (cell < 151) { h = cell - 101; w = 0; }
    else                 { h = cell - 150; w = 50; }
    ((float4*)(g_xpad + ((size_t)(b * PAD + h) * PAD + w) * C_))[q] =
        make_float4(0.f, 0.f, 0.f, 0.f);
}

__global__ void prep_wb_kernel(const float* __restrict__ w) {
    int idx = blockIdx.x * blockDim.x + threadIdx.x;   // idx = k*256 + o
    if (idx < KTOT * O_) {
        int o = idx & 255;
        int k = idx >> 8;
        int tap = k >> 8, c = k & 255;
        g_wbT[idx] = to_tf32(w[(o * C_ + c) * 7 + tap]);
    }
}

__global__ void prep_x_kernel(const float* __restrict__ x) {
    __shared__ float tile[32][33];
    const int b = blockIdx.z, c0 = blockIdx.y * 32, hw0 = blockIdx.x * 32;
    const int tx = threadIdx.x, ty = threadIdx.y;
#pragma unroll
    for (int i = 0; i < 4; i++) {
        int c = c0 + ty + i * 8, hw = hw0 + tx;
        tile[ty + i * 8][tx] = (hw < P_) ? x[((size_t)b * C_ + c) * P_ + hw] : 0.f;
    }
    __syncthreads();
#pragma unroll
    for (int i = 0; i < 4; i++) {
        int hw = hw0 + ty + i * 8;
        if (hw < P_) {
            int h = hw / H_, w = hw - h * H_;
            bool mk = (unsigned)(h + w - 24) <= 48u;
            float v = mk ? to_tf32(tile[tx][ty + i * 8]) : 0.f;
            g_xpad[((size_t)(b * PAD + h + 1) * PAD + (w + 1)) * C_ + permc(c0 + tx)] = v;
        }
    }
}

// ---------------- main: tf32 mma.sync GEMM, 128x128 tile, 3-stage cp.async ----------------
__global__ __launch_bounds__(256, 2)
void hexconv_mma_kernel(const float* __restrict__ bias, float* __restrict__ out) {
    extern __shared__ __align__(16) float smem[];
    float* sA = smem;                          // [STAGES][128][40], permuted pairs
    float* sB = smem + STAGES * A_STAGE_F;     // [STAGES][32][136], k-major
    __shared__ int rbase[MT];

    const int tid = threadIdx.x, wid = tid >> 5, lane = tid & 31;
    const int r0 = blockIdx.x * MT;
    const int nb = blockIdx.y;                 // N tile: o-offset nb*128

    if (tid < MT) {
        int r = r0 + tid;
        if (r >= M_) r = M_ - 1;
        int b = r / P_, hw = r - b * P_, h = hw / H_, w = hw - h * H_;
        rbase[tid] = ((b * PAD + h + 1) * PAD + (w + 1)) * C_;
    }
    __syncthreads();

    // A loader: thread covers 4 rows (lrow+32i), one 16B quad per row
    const int lrow = tid >> 3;                 // 0..31
    const int lq   = (tid & 7) * 4;            // 0..28 floats
    int ra[4];
#pragma unroll
    for (int i = 0; i < 4; i++) ra[i] = rbase[lrow + 32 * i];

    const uint32_t sA_u = (uint32_t)__cvta_generic_to_shared(sA);
    const uint32_t sB_u = (uint32_t)__cvta_generic_to_shared(sB);

    // warp tile: 2 (M) x 4 (N) warps, each 64x32
    const int wm = (wid & 1) * 64;
    const int wn = (wid >> 1) * 32;

    float acc[4][4][4];
#pragma unroll
    for (int mi = 0; mi < 4; mi++)
#pragma unroll
        for (int ni = 0; ni < 4; ni++)
#pragma unroll
            for (int j = 0; j < 4; j++) acc[mi][ni][j] = 0.f;

    auto load_stage = [&](int s, int ch) {
        const int k0 = ch * KC;
        const int offA = c_tapoff[k0 >> 8] + (k0 & 255) + lq;
#pragma unroll
        for (int i = 0; i < 4; i++) {
            uint32_t dA = sA_u + (uint32_t)(s * A_STAGE_F + (lrow + 32 * i) * A_STRIDE + lq) * 4u;
            CP_ASYNC16(dA, g_xpad + ra[i] + offA);
        }
        // B: 32 k-rows x 128 o; thread covers row lrow, quads lq + 32i
#pragma unroll
        for (int i = 0; i < 4; i++) {
            uint32_t dB = sB_u + (uint32_t)(s * B_STAGE_F + lrow * B_STRIDE + lq + 32 * i) * 4u;
            CP_ASYNC16(dB, g_wbT + (size_t)(k0 + lrow) * O_ + nb * 128 + lq + 32 * i);
        }
    };

#pragma unroll
    for (int s = 0; s < STAGES - 1; s++) { load_stage(s, s); CP_COMMIT(); }

    for (int ch = 0; ch < NCHUNK; ch++) {
        CP_WAIT(STAGES - 2);
        __syncthreads();
        const int pre = ch + STAGES - 1;
        if (pre < NCHUNK) load_stage(pre % STAGES, pre);
        CP_COMMIT();

        const float* A  = sA + (ch % STAGES) * A_STAGE_F;
        const float* Bm = sB + (ch % STAGES) * B_STAGE_F;
#pragma unroll
        for (int kk = 0; kk < 4; kk++) {
            const int kp = kk * 8 + 2 * (lane & 3);   // permuted pair position (A)
            const int kb = kk * 8 + (lane & 3);       // canonical k (B)
            uint32_t af[4][4], bf[4][2];
#pragma unroll
            for (int mi = 0; mi < 4; mi++) {
                int m0 = wm + mi * 16 + (lane >> 2);
                float2 alo = *(const float2*)&A[m0 * A_STRIDE + kp];       // (kb, kb+4)
                float2 ahi = *(const float2*)&A[(m0 + 8) * A_STRIDE + kp];
                af[mi][0] = __float_as_uint(alo.x);
                af[mi][1] = __float_as_uint(ahi.x);
                af[mi][2] = __float_as_uint(alo.y);
                af[mi][3] = __float_as_uint(ahi.y);
            }
#pragma unroll
            for (int ni = 0; ni < 4; ni++) {
                int n0 = wn + ni * 8 + (lane >> 2);
                bf[ni][0] = __float_as_uint(Bm[kb * B_STRIDE + n0]);
                bf[ni][1] = __float_as_uint(Bm[(kb + 4) * B_STRIDE + n0]);
            }
#pragma unroll
            for (int mi = 0; mi < 4; mi++)
#pragma unroll
                for (int ni = 0; ni < 4; ni++)
                    mma8(acc[mi][ni], af[mi], bf[ni]);
        }
    }

    // ---- epilogue: acc -> smem [o][m] (stride 132), then coalesced store ----
    __syncthreads();
    float* ep = smem;                     // 128*132 floats = 67.6 KB < 111 KB
#pragma unroll
    for (int mi = 0; mi < 4; mi++) {
        int rrow = wm + mi * 16 + (lane >> 2);
#pragma unroll
        for (int ni = 0; ni < 4; ni++) {
            int o = wn + ni * 8 + 2 * (lane & 3);
            ep[o * 132 + rrow]           = acc[mi][ni][0];
            ep[(o + 1) * 132 + rrow]     = acc[mi][ni][1];
            ep[o * 132 + rrow + 8]       = acc[mi][ni][2];
            ep[(o + 1) * 132 + rrow + 8] = acc[mi][ni][3];
        }
    }
    __syncthreads();

    for (int o = wid; o < 128; o += 8) {
        float bv = __ldg(bias + nb * 128 + o);
#pragma unroll
        for (int mb = 0; mb < 128; mb += 32) {
            int m = mb + lane;
            int r = r0 + m;
            if (r < M_) {
                int b = r / P_, hw = r - b * P_, h = hw / H_, w = hw - h * H_;
                bool mk = (unsigned)(h + w - 24) <= 48u;
                float v = mk ? (ep[o * 132 + m] + bv) : 0.f;
                out[((size_t)b * O_ + nb * 128 + o) * P_ + hw] = v;
            }
        }
    }
}

// ---------------- launcher ----------------
extern "C" void kernel_launch(void* const* d_in, const int* in_sizes, int n_in,
                              void* d_out, int out_size) {
    const float* x    = (const float*)d_in[0];   // [32,256,49,49]
    const float* wgt  = (const float*)d_in[1];   // [256,256,7]
    const float* bias = (const float*)d_in[2];   // [256]
    float* out = (float*)d_out;

    { // prep
        int nh = B_ * 200 * 64;
        zero_halo_kernel<<<(nh + 255) / 256, 256>>>();
        int nw = KTOT * O_;
        prep_wb_kernel<<<(nw + 255) / 256, 256>>>(wgt);
        dim3 g((P_ + 31) / 32, C_ / 32, B_);
        prep_x_kernel<<<g, dim3(32, 8)>>>(x);
    }

    cudaFuncSetAttribute(hexconv_mma_kernel,
                         cudaFuncAttributeMaxDynamicSharedMemorySize, DYN_SMEM);
    dim3 grid(GRID_M, 2);
    hexconv_mma_kernel<<<grid, 256, DYN_SMEM>>>(bias, out);
}